// round 11
// baseline (speedup 1.0000x reference)
#include <cuda_runtime.h>
#include <cuda_bf16.h>
#include <cstdint>

// ---------------- problem constants ----------------
#define NPAIRS 4096
#define TWO_N  8192
#define DIM    256
#define NT     64          // 8192/128 tiles per side
#define NTRI   2080        // NT*(NT+1)/2 upper-triangular tiles
#define COS_EPS 1e-8f

// ---------------- scratch (device globals, no allocation) ----------------
__device__ __align__(256) uint32_t g_nhat[TWO_N * DIM / 4]; // normalized reps, e4m3 (2MB)
__device__ float g_rowsum[TWO_N];
__device__ float g_pos[NPAIRS];
__device__ unsigned int g_done;                              // zero-init; reset by k_norm

// ---------------- PTX helpers (sm_103 base target: ldmatrix + legacy mma + cp.async) -
__device__ __forceinline__ uint32_t smem_u32(const void* p) {
    uint32_t a;
    asm("{ .reg .u64 t; cvta.to.shared.u64 t, %1; cvt.u32.u64 %0, t; }" : "=r"(a) : "l"(p));
    return a;
}

__device__ __forceinline__ void ldsm_x4(uint32_t addr, uint32_t* r) {
    asm volatile("ldmatrix.sync.aligned.m8n8.x4.shared.b16 {%0,%1,%2,%3}, [%4];"
        : "=r"(r[0]), "=r"(r[1]), "=r"(r[2]), "=r"(r[3]) : "r"(addr));
}

// fp8 e4m3 MMA: fragment byte-layout matches b16 ldmatrix loads exactly.
__device__ __forceinline__ void mma16832_e4m3(float* d, const uint32_t* a, const uint32_t* b) {
    asm volatile("mma.sync.aligned.m16n8k32.row.col.f32.e4m3.e4m3.f32 "
        "{%0,%1,%2,%3}, {%4,%5,%6,%7}, {%8,%9}, {%0,%1,%2,%3};"
        : "+f"(d[0]), "+f"(d[1]), "+f"(d[2]), "+f"(d[3])
        : "r"(a[0]), "r"(a[1]), "r"(a[2]), "r"(a[3]), "r"(b[0]), "r"(b[1]));
}

__device__ __forceinline__ void cp_async16(uint32_t dst, const void* src) {
    asm volatile("cp.async.ca.shared.global [%0], [%1], 16;" :: "r"(dst), "l"(src) : "memory");
}

__device__ __forceinline__ uint32_t pack_e4m3x4(float x0, float x1, float x2, float x3) {
    uint16_t lo, hi;
    asm("cvt.rn.satfinite.e4m3x2.f32 %0, %1, %2;" : "=h"(lo) : "f"(x1), "f"(x0));
    asm("cvt.rn.satfinite.e4m3x2.f32 %0, %1, %2;" : "=h"(hi) : "f"(x3), "f"(x2));
    return (uint32_t)lo | ((uint32_t)hi << 16);
}

// ---------------- kernel 1: normalize + positives (fp32, exact) + scratch reset -----
__global__ void k_norm(const float* __restrict__ zis, const float* __restrict__ zjs) {
    int tid = threadIdx.x;
    int gid = blockIdx.x * 256 + tid;
    if (gid < TWO_N) g_rowsum[gid] = 0.0f;
    if (gid == 0) g_done = 0u;

    int w = blockIdx.x * 8 + (tid >> 5);   // pair index 0..4095
    int lane = tid & 31;

    const float4* zi = (const float4*)zis + (size_t)w * 64;
    const float4* zj = (const float4*)zjs + (size_t)w * 64;
    float4 a0 = zi[lane], a1 = zi[lane + 32];
    float4 b0 = zj[lane], b1 = zj[lane + 32];

    float si = a0.x*a0.x + a0.y*a0.y + a0.z*a0.z + a0.w*a0.w
             + a1.x*a1.x + a1.y*a1.y + a1.z*a1.z + a1.w*a1.w;
    float sj = b0.x*b0.x + b0.y*b0.y + b0.z*b0.z + b0.w*b0.w
             + b1.x*b1.x + b1.y*b1.y + b1.z*b1.z + b1.w*b1.w;
    float dv = a0.x*b0.x + a0.y*b0.y + a0.z*b0.z + a0.w*b0.w
             + a1.x*b1.x + a1.y*b1.y + a1.z*b1.z + a1.w*b1.w;
    #pragma unroll
    for (int o = 16; o; o >>= 1) {
        si += __shfl_xor_sync(0xFFFFFFFFu, si, o);
        sj += __shfl_xor_sync(0xFFFFFFFFu, sj, o);
        dv += __shfl_xor_sync(0xFFFFFFFFu, dv, o);
    }
    float ni = sqrtf(si), nj = sqrtf(sj);
    if (lane == 0) g_pos[w] = dv / fmaxf(ni * nj, COS_EPS);

    float ii = 1.0f / ni, ji = 1.0f / nj;
    // reps = [zjs ; zis]: row w <- zjs[w]/nj, row w+NPAIRS <- zis[w]/ni  (e4m3)
    uint32_t* rj = g_nhat + (size_t)w * 64;
    uint32_t* ri = g_nhat + (size_t)(w + NPAIRS) * 64;
    rj[lane]      = pack_e4m3x4(b0.x*ji, b0.y*ji, b0.z*ji, b0.w*ji);
    rj[lane + 32] = pack_e4m3x4(b1.x*ji, b1.y*ji, b1.z*ji, b1.w*ji);
    ri[lane]      = pack_e4m3x4(a0.x*ii, a0.y*ii, a0.z*ii, a0.w*ii);
    ri[lane + 32] = pack_e4m3x4(a1.x*ii, a1.y*ii, a1.z*ii, a1.w*ii);
}

// ---------------- kernel 2: GEMM tile + exp + partial sums + fused final reduction ---
// Triangular tiles tm<=tn, 256 threads, warp grid 2(m)x4(n), warp tile 64x32.
// SMEM: two 128x256B e4m3 tiles (dynamic) + 256-float reduction array (static).
// 4-stage split-K cp.async pipeline (64B of K per commit group).
static constexpr uint32_t TILEB = 128u * 256u;      // 32 KB per tile
static constexpr uint32_t SMEM_TOTAL = 2u * TILEB;  // 64 KB dynamic -> occupancy 2

__global__ __launch_bounds__(256, 2) void k_gemm(float* __restrict__ out) {
    extern __shared__ uint8_t smem[];
    __shared__ float red[256];               // [0:128) row partials, [128:256) col partials
    __shared__ unsigned int lastFlag;

    // triangular decode: linear t -> (tm, tn), tm <= tn
    int t = blockIdx.x;
    int tm = (int)(64.5f - sqrtf(64.5f * 64.5f - 2.0f * (float)t));
    while (NT * tm - tm * (tm - 1) / 2 > t) --tm;
    while (NT * (tm + 1) - (tm + 1) * tm / 2 <= t) ++tm;
    int tn = tm + (t - (NT * tm - tm * (tm - 1) / 2));

    int tid = threadIdx.x, wid = tid >> 5, lane = tid & 31;
    int wm = wid >> 2, wn = wid & 3;         // warp grid 2(m) x 4(n); warp tile 64x32
    int g = lane >> 2, q = lane & 3;
    bool diag = (tm == tn);

    red[tid] = 0.f;                          // zeroed during load phase (sync via pipeline)
    uint32_t sbase = smem_u32(smem);

    // ---- global -> shared via cp.async: 4 commit groups, 4 of 16 chunks each ----
    const uint4* __restrict__ src = (const uint4*)g_nhat; // 16 x 16B chunks per row
    #pragma unroll
    for (int h = 0; h < 4; ++h) {
        #pragma unroll
        for (int it = 0; it < 2; ++it) {     // 128 rows x 4 chunks per group per tile
            int idx = it * 256 + tid;        // 0..511
            int r = idx >> 2, kv = (idx & 3) + h * 4;
            uint32_t off = (uint32_t)(r * 256 + kv * 16);
            uint32_t sw = off ^ ((uint32_t)(r & 7) << 4);
            cp_async16(sbase + sw, src + (size_t)(tm * 128 + r) * 16 + kv);
            if (!diag)
                cp_async16(sbase + TILEB + sw, src + (size_t)(tn * 128 + r) * 16 + kv);
        }
        asm volatile("cp.async.commit_group;" ::: "memory");
    }

    uint32_t sA = sbase;
    uint32_t sB = diag ? sA : (sA + TILEB);

    float acc[4][4][4];
    #pragma unroll
    for (int i = 0; i < 4; ++i)
        #pragma unroll
        for (int j = 0; j < 4; ++j)
            #pragma unroll
            for (int x = 0; x < 4; ++x) acc[i][j][x] = 0.f;

    int l7 = lane & 7;
    int ra_base = wm * 64 + l7 + ((lane >> 3) & 1) * 8;  // A rows
    int ka_base = (lane >> 4) * 16;                      // A 16B sub-chunk of 32B k-step
    int rb_base = wn * 32 + l7 + (lane >> 4) * 8;        // B n-rows
    int kb_base = ((lane >> 3) & 1) * 16;                // B 16B sub-chunk

    #pragma unroll
    for (int h = 0; h < 4; ++h) {
        switch (h) {                                     // progressive pipeline drain
            case 0: asm volatile("cp.async.wait_group 3;" ::: "memory"); break;
            case 1: asm volatile("cp.async.wait_group 2;" ::: "memory"); break;
            case 2: asm volatile("cp.async.wait_group 1;" ::: "memory"); break;
            default: asm volatile("cp.async.wait_group 0;" ::: "memory"); break;
        }
        __syncthreads();
        #pragma unroll
        for (int k2 = 0; k2 < 2; ++k2) {                 // k-step = 32 fp8 = 32 bytes
            int kk = h * 2 + k2;
            uint32_t af[4][4];
            #pragma unroll
            for (int i = 0; i < 4; ++i) {
                int r = ra_base + i * 16;
                uint32_t off = (uint32_t)(r * 256 + kk * 32 + ka_base);
                ldsm_x4(sA + (off ^ ((uint32_t)(r & 7) << 4)), af[i]);
            }
            uint32_t bf[2][4];
            #pragma unroll
            for (int j2 = 0; j2 < 2; ++j2) {
                int r = rb_base + j2 * 16;
                uint32_t off = (uint32_t)(r * 256 + kk * 32 + kb_base);
                ldsm_x4(sB + (off ^ ((uint32_t)(r & 7) << 4)), bf[j2]);
            }
            #pragma unroll
            for (int i = 0; i < 4; ++i)
                #pragma unroll
                for (int j = 0; j < 4; ++j)
                    mma16832_e4m3(acc[i][j], af[i], &bf[j >> 1][(j & 1) * 2]);
        }
    }

    // ---- epilogue: exp + row/col partial sums into static smem (no tile aliasing) ----
    float rs[4][2], cs[4][2];
    #pragma unroll
    for (int i = 0; i < 4; ++i) { rs[i][0] = 0.f; rs[i][1] = 0.f; }
    #pragma unroll
    for (int j = 0; j < 4; ++j) { cs[j][0] = 0.f; cs[j][1] = 0.f; }

    #pragma unroll
    for (int i = 0; i < 4; ++i) {
        int R0 = wm * 64 + i * 16 + g, R1 = R0 + 8;
        #pragma unroll
        for (int j = 0; j < 4; ++j) {
            int C0 = wn * 32 + j * 8 + 2 * q, C1 = C0 + 1;
            float e00 = __expf(2.0f * acc[i][j][0]);  // logits = sim / 0.5
            float e01 = __expf(2.0f * acc[i][j][1]);
            float e10 = __expf(2.0f * acc[i][j][2]);
            float e11 = __expf(2.0f * acc[i][j][3]);
            if (diag) {                               // mask self-diagonal
                if (R0 == C0) e00 = 0.f;
                if (R0 == C1) e01 = 0.f;
                if (R1 == C0) e10 = 0.f;
                if (R1 == C1) e11 = 0.f;
            }
            rs[i][0] += e00 + e01;  rs[i][1] += e10 + e11;
            cs[j][0] += e00 + e10;  cs[j][1] += e01 + e11;
        }
    }
    // row partials: lanes sharing g share rows -> reduce over q
    #pragma unroll
    for (int i = 0; i < 4; ++i)
        #pragma unroll
        for (int h = 0; h < 2; ++h) {
            float v = rs[i][h];
            v += __shfl_xor_sync(0xFFFFFFFFu, v, 1);
            v += __shfl_xor_sync(0xFFFFFFFFu, v, 2);
            if (q == 0) atomicAdd(&red[wm * 64 + i * 16 + g + h * 8], v);
        }
    // col partials: lanes sharing q share cols -> reduce over g (off-diagonal tiles)
    if (!diag) {
        #pragma unroll
        for (int j = 0; j < 4; ++j)
            #pragma unroll
            for (int h = 0; h < 2; ++h) {
                float v = cs[j][h];
                v += __shfl_xor_sync(0xFFFFFFFFu, v, 4);
                v += __shfl_xor_sync(0xFFFFFFFFu, v, 8);
                v += __shfl_xor_sync(0xFFFFFFFFu, v, 16);
                if (g == 0) atomicAdd(&red[128 + wn * 32 + j * 8 + 2 * q + h], v);
            }
    }
    __syncthreads();
    if (tid < 128) {
        atomicAdd(&g_rowsum[tm * 128 + tid], red[tid]);
        if (!diag) atomicAdd(&g_rowsum[tn * 128 + tid], red[128 + tid]);
    }

    // ---- last-CTA-done: fused final reduction (threadFenceReduction pattern) ----
    __threadfence();
    __syncthreads();
    if (tid == 0) {
        unsigned int prev = atomicAdd(&g_done, 1u);
        lastFlag = (prev == NTRI - 1u) ? 1u : 0u;
    }
    __syncthreads();
    if (lastFlag) {
        __threadfence();                     // acquire: see all CTAs' rowsum atomics
        float v = 0.f;
        #pragma unroll
        for (int it = 0; it < 32; ++it) {
            int r = tid + it * 256;
            v += __logf(g_rowsum[r]) - 2.0f * g_pos[r & (NPAIRS - 1)];
        }
        #pragma unroll
        for (int o = 16; o; o >>= 1) v += __shfl_xor_sync(0xFFFFFFFFu, v, o);
        __syncthreads();                     // red reuse safe after this
        if (lane == 0) red[wid] = v;
        __syncthreads();
        if (tid == 0) {
            float s = red[0] + red[1] + red[2] + red[3]
                    + red[4] + red[5] + red[6] + red[7];
            out[0] = s / (float)TWO_N;
        }
    }
}

// ---------------- launch ----------------
extern "C" void kernel_launch(void* const* d_in, const int* in_sizes, int n_in,
                              void* d_out, int out_size) {
    const float* zis = (const float*)d_in[0];
    const float* zjs = (const float*)d_in[1];
    float* out = (float*)d_out;

    cudaFuncSetAttribute(k_gemm, cudaFuncAttributeMaxDynamicSharedMemorySize, SMEM_TOTAL);

    k_norm<<<512, 256>>>(zis, zjs);
    k_gemm<<<NTRI, 256, SMEM_TOTAL>>>(out);
}